// round 1
// baseline (speedup 1.0000x reference)
#include <cuda_runtime.h>
#include <math.h>

// ---------------------------------------------------------------------------
// Problem constants
// ---------------------------------------------------------------------------
#define BATCH 2048
#define TSTEPS 25
#define D0 100   // noise dim (K of layer 1)
#define D1 128
#define D2 256
#define D3 512
#define D4 1024
#define D5 784

#define BETA 0.95f
#define THRESH 1.0f

// ---------------------------------------------------------------------------
// Persistent device state (no allocation allowed)
// ---------------------------------------------------------------------------
// membrane potentials, one slab per layer, flat
#define M1OFF 0
#define M2OFF (M1OFF + BATCH*D1)
#define M3OFF (M2OFF + BATCH*D2)
#define M4OFF (M3OFF + BATCH*D3)
#define M5OFF (M4OFF + BATCH*D4)
#define MTOTAL (M5OFF + BATCH*D5)
__device__ float g_mem[MTOTAL];

// activations: cur1 (constant across steps) + spike outputs of layers 1..4
#define A_CUR1 0
#define A_SPK1 (A_CUR1 + BATCH*D1)
#define A_SPK2 (A_SPK1 + BATCH*D1)
#define A_SPK3 (A_SPK2 + BATCH*D2)
#define A_SPK4 (A_SPK3 + BATCH*D3)
#define ATOTAL (A_SPK4 + BATCH*D4)
__device__ float g_act[ATOTAL];

// ---------------------------------------------------------------------------
// Zero the membrane state (fresh every kernel_launch call -> deterministic)
// ---------------------------------------------------------------------------
__global__ void zero_mem_kernel() {
    int stride = gridDim.x * blockDim.x;
    for (int i = blockIdx.x * blockDim.x + threadIdx.x; i < MTOTAL; i += stride)
        g_mem[i] = 0.0f;
}

// ---------------------------------------------------------------------------
// LIF elementwise for layer 1 (cur1 is precomputed, reused each step)
// ---------------------------------------------------------------------------
__global__ void lif1_kernel() {
    int i = blockIdx.x * blockDim.x + threadIdx.x;
    if (i < BATCH * D1) {
        float cur   = g_act[A_CUR1 + i];
        float m_old = g_mem[M1OFF + i];
        float reset = (m_old - THRESH > 0.0f) ? 1.0f : 0.0f;
        float m_new = BETA * m_old + cur - reset * THRESH;
        g_mem[M1OFF + i] = m_new;
        g_act[A_SPK1 + i] = (m_new - THRESH > 0.0f) ? 1.0f : 0.0f;
    }
}

// ---------------------------------------------------------------------------
// Fused GEMM + bias + ReLU (+ LIF) kernel.
//   C[M,N] = A[M,K] @ W[N,K]^T      (both K-major: pure dot products)
// MODE 0: write relu(acc+b) to g_act[out_off]                  (cur1 precompute)
// MODE 1: LIF update (mem in g_mem[mem_off]), spike -> g_act[out_off]
// MODE 2: LIF update, spike -> spk_ext, tanh(mem_new) -> mem_ext   (layer 5)
// ---------------------------------------------------------------------------
#define BM 128
#define BN 64
#define BK 16
#define TM 8
#define TN 4
// 256 threads: 16 (N dir) x 16 (M dir)

template <int MODE>
__global__ __launch_bounds__(256)
void gemm_lif_kernel(const float* __restrict__ Aext, int a_off,
                     const float* __restrict__ W, const float* __restrict__ bias,
                     int mem_off, int out_off,
                     float* __restrict__ spk_ext, float* __restrict__ mem_ext,
                     int N, int K)
{
    __shared__ float As[BK][BM];
    __shared__ float Ws[BK][BN];

    const float* A = Aext ? Aext : &g_act[a_off];

    int tid = threadIdx.x;
    int tx = tid & 15;   // N direction (x TN)
    int ty = tid >> 4;   // M direction (x TM)
    int m0 = blockIdx.y * BM;
    int n0 = blockIdx.x * BN;

    float acc[TM][TN];
#pragma unroll
    for (int i = 0; i < TM; i++)
#pragma unroll
        for (int j = 0; j < TN; j++) acc[i][j] = 0.0f;

    for (int k0 = 0; k0 < K; k0 += BK) {
        // ---- load A tile (128 x 16) : 512 float4, 2 per thread ----
#pragma unroll
        for (int it = 0; it < 2; it++) {
            int f4  = it * 256 + tid;
            int row = f4 >> 2;          // 0..127
            int q   = f4 & 3;           // which float4 in the 16-wide k slice
            int gk  = k0 + q * 4;
            float4 v = make_float4(0.f, 0.f, 0.f, 0.f);
            if (gk < K)   // all K are multiples of 4, no straddle
                v = *reinterpret_cast<const float4*>(&A[(size_t)(m0 + row) * K + gk]);
            As[q*4+0][row] = v.x; As[q*4+1][row] = v.y;
            As[q*4+2][row] = v.z; As[q*4+3][row] = v.w;
        }
        // ---- load W tile (64 x 16) : 256 float4, 1 per thread ----
        {
            int row = tid >> 2;         // 0..63
            int q   = tid & 3;
            int gn  = n0 + row;
            int gk  = k0 + q * 4;
            float4 v = make_float4(0.f, 0.f, 0.f, 0.f);
            if (gn < N && gk < K)
                v = *reinterpret_cast<const float4*>(&W[(size_t)gn * K + gk]);
            Ws[q*4+0][row] = v.x; Ws[q*4+1][row] = v.y;
            Ws[q*4+2][row] = v.z; Ws[q*4+3][row] = v.w;
        }
        __syncthreads();

#pragma unroll
        for (int kk = 0; kk < BK; kk++) {
            float a[TM], w[TN];
#pragma unroll
            for (int i = 0; i < TM; i++) a[i] = As[kk][ty * TM + i];
#pragma unroll
            for (int j = 0; j < TN; j++) w[j] = Ws[kk][tx * TN + j];
#pragma unroll
            for (int i = 0; i < TM; i++)
#pragma unroll
                for (int j = 0; j < TN; j++)
                    acc[i][j] = fmaf(a[i], w[j], acc[i][j]);
        }
        __syncthreads();
    }

    // ---- epilogue ----
    float bvals[TN];
#pragma unroll
    for (int j = 0; j < TN; j++) {
        int gn = n0 + tx * TN + j;
        bvals[j] = (gn < N) ? bias[gn] : 0.0f;
    }

#pragma unroll
    for (int i = 0; i < TM; i++) {
        int gm = m0 + ty * TM + i;
#pragma unroll
        for (int j = 0; j < TN; j++) {
            int gn = n0 + tx * TN + j;
            if (gn >= N) continue;
            size_t idx = (size_t)gm * N + gn;
            float cur = fmaxf(acc[i][j] + bvals[j], 0.0f);
            if (MODE == 0) {
                g_act[out_off + idx] = cur;
            } else {
                float m_old = g_mem[mem_off + idx];
                float reset = (m_old - THRESH > 0.0f) ? 1.0f : 0.0f;
                float m_new = BETA * m_old + cur - reset * THRESH;
                g_mem[mem_off + idx] = m_new;
                float s = (m_new - THRESH > 0.0f) ? 1.0f : 0.0f;
                if (MODE == 1) {
                    g_act[out_off + idx] = s;
                } else {
                    spk_ext[idx] = s;
                    mem_ext[idx] = tanhf(m_new);
                }
            }
        }
    }
}

// ---------------------------------------------------------------------------
// Host launcher
// ---------------------------------------------------------------------------
static inline int ntiles(int n) { return (n + BN - 1) / BN; }

extern "C" void kernel_launch(void* const* d_in, const int* in_sizes, int n_in,
                              void* d_out, int out_size)
{
    const float* x  = (const float*)d_in[0];
    const float* W1 = (const float*)d_in[1];
    const float* b1 = (const float*)d_in[2];
    const float* W2 = (const float*)d_in[3];
    const float* b2 = (const float*)d_in[4];
    const float* W3 = (const float*)d_in[5];
    const float* b3 = (const float*)d_in[6];
    const float* W4 = (const float*)d_in[7];
    const float* b4 = (const float*)d_in[8];
    const float* W5 = (const float*)d_in[9];
    const float* b5 = (const float*)d_in[10];

    float* out      = (float*)d_out;
    float* out_spk  = out;                                   // [25, 2048, 784]
    float* out_mem  = out + (size_t)TSTEPS * BATCH * D5;     // [25, 2048, 784]

    const int MB = BATCH / BM;  // 16 M-tiles

    // 1) fresh membrane state
    zero_mem_kernel<<<1024, 256>>>();

    // 2) constant layer-1 current: cur1 = relu(x @ W1^T + b1)
    gemm_lif_kernel<0><<<dim3(ntiles(D1), MB), 256>>>(
        x, 0, W1, b1, 0, A_CUR1, nullptr, nullptr, D1, D0);

    // 3) time loop
    for (int t = 0; t < TSTEPS; t++) {
        lif1_kernel<<<(BATCH * D1 + 255) / 256, 256>>>();

        gemm_lif_kernel<1><<<dim3(ntiles(D2), MB), 256>>>(
            nullptr, A_SPK1, W2, b2, M2OFF, A_SPK2, nullptr, nullptr, D2, D1);

        gemm_lif_kernel<1><<<dim3(ntiles(D3), MB), 256>>>(
            nullptr, A_SPK2, W3, b3, M3OFF, A_SPK3, nullptr, nullptr, D3, D2);

        gemm_lif_kernel<1><<<dim3(ntiles(D4), MB), 256>>>(
            nullptr, A_SPK3, W4, b4, M4OFF, A_SPK4, nullptr, nullptr, D4, D3);

        gemm_lif_kernel<2><<<dim3(ntiles(D5), MB), 256>>>(
            nullptr, A_SPK4, W5, b5, M5OFF, 0,
            out_spk + (size_t)t * BATCH * D5,
            out_mem + (size_t)t * BATCH * D5, D5, D4);
    }
}

// round 5
// speedup vs baseline: 3.5510x; 3.5510x over previous
#include <cuda_runtime.h>
#include <cuda_bf16.h>
#include <stdint.h>
#include <math.h>

#define BATCH 2048
#define TSTEPS 25
#define D0 100
#define D1 128
#define D2 256
#define D3 512
#define D4 1024
#define D5 784
#define D5P 832

#define BETA 0.95f
#define THRESH 1.0f

// ------------------------- persistent device state -------------------------
#define M1OFF 0
#define M2OFF (M1OFF + BATCH*D1)
#define M3OFF (M2OFF + BATCH*D2)
#define M4OFF (M3OFF + BATCH*D3)
#define M5OFF (M4OFF + BATCH*D4)
#define MTOTAL (M5OFF + BATCH*D5)
__device__ float g_mem[MTOTAL];

__device__ float g_cur1[BATCH * D1];

#define S1OFF 0
#define S2OFF (S1OFF + BATCH*D1)
#define S3OFF (S2OFF + BATCH*D2)
#define S4OFF (S3OFF + BATCH*D3)
#define STOTAL (S4OFF + BATCH*D4)
__device__ __nv_bfloat16 g_spk[STOTAL];

#define W2OFF 0
#define W3OFF (W2OFF + D2*D1)
#define W4OFF (W3OFF + D3*D2)
#define W5OFF (W4OFF + D4*D3)
#define WTOTAL (W5OFF + D5P*D4)
__device__ __nv_bfloat16 g_w1[WTOTAL];   // hi
__device__ __nv_bfloat16 g_w2[WTOTAL];   // mid
__device__ __nv_bfloat16 g_w3[WTOTAL];   // lo

// ------------------------------ utilities ----------------------------------
__global__ void zero_mem_kernel()
{
    int stride = gridDim.x * blockDim.x;
    for (int i = blockIdx.x * blockDim.x + threadIdx.x; i < MTOTAL; i += stride) {
        g_mem[i] = 0.0f;
    }
}

// 3-term bf16 split: w = h1 + h2 + h3 + O(2^-27 |w|)
__global__ void split_w_kernel(const float* __restrict__ W, int N, int K,
                               int Npad, int off)
{
    int stride = gridDim.x * blockDim.x;
    int total = Npad * K;
    int nk = N * K;
    for (int i = blockIdx.x * blockDim.x + threadIdx.x; i < total; i += stride) {
        float w = 0.0f;
        if (i < nk) { w = W[i]; }
        __nv_bfloat16 h1 = __float2bfloat16(w);
        float r1 = w - __bfloat162float(h1);
        __nv_bfloat16 h2 = __float2bfloat16(r1);
        float r2 = r1 - __bfloat162float(h2);
        __nv_bfloat16 h3 = __float2bfloat16(r2);
        g_w1[off + i] = h1;
        g_w2[off + i] = h2;
        g_w3[off + i] = h3;
    }
}

__global__ void lif1_kernel()
{
    int i = blockIdx.x * blockDim.x + threadIdx.x;
    if (i < BATCH * D1) {
        float cval = g_cur1[i];
        float mold = g_mem[M1OFF + i];
        float rst = 0.0f;
        if (mold > THRESH) { rst = 1.0f; }
        float mnew = BETA * mold + cval - rst * THRESH;
        g_mem[M1OFF + i] = mnew;
        float sp = 0.0f;
        if (mnew > THRESH) { sp = 1.0f; }
        g_spk[S1OFF + i] = __float2bfloat16(sp);
    }
}

// ----------------- layer-1 fp32 GEMM (runs once per launch) ----------------
__global__ __launch_bounds__(256)
void cur1_kernel(const float* __restrict__ A, const float* __restrict__ W,
                 const float* __restrict__ bias)
{
    const int N = D1;
    const int K = D0;
    __shared__ float As[16][128];
    __shared__ float Ws[16][64];

    int tid = threadIdx.x;
    int tx = tid & 15;
    int ty = tid >> 4;
    int m0 = blockIdx.y * 128;
    int n0 = blockIdx.x * 64;

    float acc[8][4];
#pragma unroll
    for (int i = 0; i < 8; i++) {
#pragma unroll
        for (int j = 0; j < 4; j++) { acc[i][j] = 0.0f; }
    }

    for (int k0 = 0; k0 < K; k0 += 16) {
#pragma unroll
        for (int it = 0; it < 2; it++) {
            int f4 = it * 256 + tid;
            int row = f4 >> 2;
            int q = f4 & 3;
            int gk = k0 + q * 4;
            float4 v = make_float4(0.f, 0.f, 0.f, 0.f);
            if (gk < K) {
                v = *reinterpret_cast<const float4*>(&A[(size_t)(m0 + row) * K + gk]);
            }
            As[q*4+0][row] = v.x;
            As[q*4+1][row] = v.y;
            As[q*4+2][row] = v.z;
            As[q*4+3][row] = v.w;
        }
        {
            int row = tid >> 2;
            int q = tid & 3;
            int gk = k0 + q * 4;
            float4 v = make_float4(0.f, 0.f, 0.f, 0.f);
            if (gk < K) {
                v = *reinterpret_cast<const float4*>(&W[(size_t)(n0 + row) * K + gk]);
            }
            Ws[q*4+0][row] = v.x;
            Ws[q*4+1][row] = v.y;
            Ws[q*4+2][row] = v.z;
            Ws[q*4+3][row] = v.w;
        }
        __syncthreads();
#pragma unroll
        for (int kk = 0; kk < 16; kk++) {
            float av[8];
            float wv[4];
#pragma unroll
            for (int i = 0; i < 8; i++) { av[i] = As[kk][ty * 8 + i]; }
#pragma unroll
            for (int j = 0; j < 4; j++) { wv[j] = Ws[kk][tx * 4 + j]; }
#pragma unroll
            for (int i = 0; i < 8; i++) {
#pragma unroll
                for (int j = 0; j < 4; j++) {
                    acc[i][j] = fmaf(av[i], wv[j], acc[i][j]);
                }
            }
        }
        __syncthreads();
    }

#pragma unroll
    for (int i = 0; i < 8; i++) {
        int gm = m0 + ty * 8 + i;
#pragma unroll
        for (int j = 0; j < 4; j++) {
            int gn = n0 + tx * 4 + j;
            g_cur1[(size_t)gm * N + gn] = fmaxf(acc[i][j] + bias[gn], 0.0f);
        }
    }
}

// ------------------- tensor-core GEMM + fused LIF --------------------------
#define SWZ(x) ((x) ^ (((x) >> 3) & 0x70))
#define STAGE_BYTES 32768

__device__ __forceinline__ void cp16(uint32_t s, const void* g)
{
    asm volatile("cp.async.cg.shared.global [%0], [%1], 16;" :: "r"(s), "l"(g));
}

__device__ __forceinline__ void ldsm4(uint32_t* r, uint32_t s)
{
    asm volatile("ldmatrix.sync.aligned.m8n8.x4.shared.b16 {%0,%1,%2,%3}, [%4];"
                 : "=r"(r[0]), "=r"(r[1]), "=r"(r[2]), "=r"(r[3]) : "r"(s));
}

__device__ __forceinline__ void mma_bf16(float* c, const uint32_t* a, const uint32_t* b)
{
    asm volatile("mma.sync.aligned.m16n8k16.row.col.f32.bf16.bf16.f32 "
                 "{%0,%1,%2,%3}, {%4,%5,%6,%7}, {%8,%9}, {%0,%1,%2,%3};"
                 : "+f"(c[0]), "+f"(c[1]), "+f"(c[2]), "+f"(c[3])
                 : "r"(a[0]), "r"(a[1]), "r"(a[2]), "r"(a[3]),
                   "r"(b[0]), "r"(b[1]));
}

template <int MODE>
__global__ __launch_bounds__(256)
void mma_lif_kernel(int aoff, int woff, const float* __restrict__ bias,
                    int memoff, int soff,
                    float* __restrict__ spk_ext, float* __restrict__ mem_ext,
                    int N, int K)
{
    extern __shared__ __align__(128) char smem_raw[];
    const uint32_t smem = (uint32_t)__cvta_generic_to_shared(smem_raw);

    const __nv_bfloat16* __restrict__ A  = g_spk + aoff;
    const __nv_bfloat16* __restrict__ P1 = g_w1 + woff;
    const __nv_bfloat16* __restrict__ P2 = g_w2 + woff;
    const __nv_bfloat16* __restrict__ P3 = g_w3 + woff;

    const int tid = threadIdx.x;
    const int lane = tid & 31;
    const int warp = tid >> 5;
    const int wm = warp >> 2;
    const int wn = warp & 3;
    const int m0 = blockIdx.y * 64;
    const int n0 = blockIdx.x * 64;

    // master fp32 accumulator (exact RN adds across k-blocks)
    float asum[2][2][4];
#pragma unroll
    for (int i = 0; i < 2; i++) {
#pragma unroll
        for (int j = 0; j < 2; j++) {
#pragma unroll
            for (int k = 0; k < 4; k++) { asum[i][j][k] = 0.0f; }
        }
    }

    const int crow = tid >> 3;
    const int ccol = tid & 7;
    const int nk = K >> 6;

    {
        uint32_t sA = smem;
        uint32_t s1 = smem + 8192;
        uint32_t s2 = smem + 16384;
        uint32_t s3 = smem + 24576;
#pragma unroll
        for (int it = 0; it < 2; it++) {
            int row = it * 32 + crow;
            uint32_t d = SWZ(row * 128 + ccol * 16);
            cp16(sA + d, A  + (size_t)(m0 + row) * K + ccol * 8);
            cp16(s1 + d, P1 + (size_t)(n0 + row) * K + ccol * 8);
            cp16(s2 + d, P2 + (size_t)(n0 + row) * K + ccol * 8);
            cp16(s3 + d, P3 + (size_t)(n0 + row) * K + ccol * 8);
        }
        asm volatile("cp.async.commit_group;");
    }

    const int arow = wm * 32 + (lane & 15);
    const int akc = lane >> 4;
    const int bq = lane >> 3;
    const int brow = wn * 16 + ((bq >> 1) << 3) + (lane & 7);
    const int bkc = bq & 1;

    for (int i = 0; i < nk; i++) {
        if (i + 1 < nk) {
            int k0 = (i + 1) << 6;
            uint32_t base = smem + ((i + 1) & 1) * STAGE_BYTES;
            uint32_t sA = base;
            uint32_t s1 = base + 8192;
            uint32_t s2 = base + 16384;
            uint32_t s3 = base + 24576;
#pragma unroll
            for (int it = 0; it < 2; it++) {
                int row = it * 32 + crow;
                uint32_t d = SWZ(row * 128 + ccol * 16);
                cp16(sA + d, A  + (size_t)(m0 + row) * K + k0 + ccol * 8);
                cp16(s1 + d, P1 + (size_t)(n0 + row) * K + k0 + ccol * 8);
                cp16(s2 + d, P2 + (size_t)(n0 + row) * K + k0 + ccol * 8);
                cp16(s3 + d, P3 + (size_t)(n0 + row) * K + k0 + ccol * 8);
            }
            asm volatile("cp.async.commit_group;");
            asm volatile("cp.async.wait_group 1;");
        } else {
            asm volatile("cp.async.wait_group 0;");
        }
        __syncthreads();

        // fresh iteration accumulators: short, well-scaled TC chains
        float accA[2][2][4];   // h1 chain
        float accB[2][2][4];   // h2 + h3 chains (small magnitude)
#pragma unroll
        for (int ii = 0; ii < 2; ii++) {
#pragma unroll
            for (int jj = 0; jj < 2; jj++) {
#pragma unroll
                for (int kk2 = 0; kk2 < 4; kk2++) {
                    accA[ii][jj][kk2] = 0.0f;
                    accB[ii][jj][kk2] = 0.0f;
                }
            }
        }

        uint32_t base = smem + (i & 1) * STAGE_BYTES;
        uint32_t sA = base;
        uint32_t s1 = base + 8192;
        uint32_t s2 = base + 16384;
        uint32_t s3 = base + 24576;
#pragma unroll
        for (int kk = 0; kk < 4; kk++) {
            uint32_t af[2][4];
            uint32_t b1[4];
            uint32_t b2[4];
            uint32_t b3[4];
#pragma unroll
            for (int mi = 0; mi < 2; mi++) {
                ldsm4(af[mi], sA + SWZ((arow + mi * 16) * 128 + (kk * 2 + akc) * 16));
            }
            ldsm4(b1, s1 + SWZ(brow * 128 + (kk * 2 + bkc) * 16));
            ldsm4(b2, s2 + SWZ(brow * 128 + (kk * 2 + bkc) * 16));
            ldsm4(b3, s3 + SWZ(brow * 128 + (kk * 2 + bkc) * 16));
#pragma unroll
            for (int mi = 0; mi < 2; mi++) {
                mma_bf16(accA[mi][0], af[mi], b1);
                mma_bf16(accA[mi][1], af[mi], b1 + 2);
                mma_bf16(accB[mi][0], af[mi], b2);
                mma_bf16(accB[mi][1], af[mi], b2 + 2);
                mma_bf16(accB[mi][0], af[mi], b3);
                mma_bf16(accB[mi][1], af[mi], b3 + 2);
            }
        }

        // fold into master accumulator with exact fp32 RN adds
#pragma unroll
        for (int ii = 0; ii < 2; ii++) {
#pragma unroll
            for (int jj = 0; jj < 2; jj++) {
#pragma unroll
                for (int kk2 = 0; kk2 < 4; kk2++) {
                    asum[ii][jj][kk2] += accA[ii][jj][kk2] + accB[ii][jj][kk2];
                }
            }
        }
        __syncthreads();
    }

    // fused LIF epilogue
    float* mem = g_mem + memoff;
#pragma unroll
    for (int mi = 0; mi < 2; mi++) {
        int rbase = m0 + wm * 32 + mi * 16 + (lane >> 2);
#pragma unroll
        for (int nf = 0; nf < 2; nf++) {
            int col = n0 + wn * 16 + nf * 8 + (lane & 3) * 2;
            if (MODE == 2) {
                if (col >= N) { continue; }
            }
            float bia0 = bias[col];
            float bia1 = bias[col + 1];
#pragma unroll
            for (int h = 0; h < 2; h++) {
                int row = rbase + h * 8;
                float cu0 = fmaxf(asum[mi][nf][h * 2 + 0] + bia0, 0.0f);
                float cu1 = fmaxf(asum[mi][nf][h * 2 + 1] + bia1, 0.0f);
                size_t idx = (size_t)row * N + col;
                float2 mo = *reinterpret_cast<float2*>(&mem[idx]);
                float rst0 = 0.0f;
                float rst1 = 0.0f;
                if (mo.x > THRESH) { rst0 = 1.0f; }
                if (mo.y > THRESH) { rst1 = 1.0f; }
                float mn0 = BETA * mo.x + cu0 - rst0 * THRESH;
                float mn1 = BETA * mo.y + cu1 - rst1 * THRESH;
                *reinterpret_cast<float2*>(&mem[idx]) = make_float2(mn0, mn1);
                float sp0 = 0.0f;
                float sp1 = 0.0f;
                if (mn0 > THRESH) { sp0 = 1.0f; }
                if (mn1 > THRESH) { sp1 = 1.0f; }
                if (MODE == 1) {
                    __nv_bfloat162 sb;
                    sb.x = __float2bfloat16(sp0);
                    sb.y = __float2bfloat16(sp1);
                    *reinterpret_cast<__nv_bfloat162*>(&g_spk[soff + idx]) = sb;
                } else {
                    *reinterpret_cast<float2*>(&spk_ext[idx]) = make_float2(sp0, sp1);
                    *reinterpret_cast<float2*>(&mem_ext[idx]) =
                        make_float2(tanhf(mn0), tanhf(mn1));
                }
            }
        }
    }
}

// ------------------------------ host launcher ------------------------------
extern "C" void kernel_launch(void* const* d_in, const int* in_sizes, int n_in,
                              void* d_out, int out_size)
{
    const float* x  = (const float*)d_in[0];
    const float* W1 = (const float*)d_in[1];
    const float* b1 = (const float*)d_in[2];
    const float* W2 = (const float*)d_in[3];
    const float* b2 = (const float*)d_in[4];
    const float* W3 = (const float*)d_in[5];
    const float* b3 = (const float*)d_in[6];
    const float* W4 = (const float*)d_in[7];
    const float* b4 = (const float*)d_in[8];
    const float* W5 = (const float*)d_in[9];
    const float* b5 = (const float*)d_in[10];

    float* out = (float*)d_out;
    float* out_spk = out;
    float* out_mem = out + (size_t)TSTEPS * BATCH * D5;

    static int smem_set = 0;
    if (smem_set == 0) {
        cudaFuncSetAttribute(mma_lif_kernel<1>,
                             cudaFuncAttributeMaxDynamicSharedMemorySize,
                             2 * STAGE_BYTES);
        cudaFuncSetAttribute(mma_lif_kernel<2>,
                             cudaFuncAttributeMaxDynamicSharedMemorySize,
                             2 * STAGE_BYTES);
        smem_set = 1;
    }

    zero_mem_kernel<<<1024, 256>>>();
    split_w_kernel<<<128, 256>>>(W2, D2, D1, D2, W2OFF);
    split_w_kernel<<<256, 256>>>(W3, D3, D2, D3, W3OFF);
    split_w_kernel<<<512, 256>>>(W4, D4, D3, D4, W4OFF);
    split_w_kernel<<<832, 256>>>(W5, D5, D4, D5P, W5OFF);

    cur1_kernel<<<dim3(2, 16), 256>>>(x, W1, b1);

    const int MB = BATCH / 64;

    for (int t = 0; t < TSTEPS; t++) {
        lif1_kernel<<<(BATCH * D1 + 255) / 256, 256>>>();

        mma_lif_kernel<1><<<dim3(D2 / 64, MB), 256, 2 * STAGE_BYTES>>>(
            S1OFF, W2OFF, b2, M2OFF, S2OFF, (float*)0, (float*)0, D2, D1);

        mma_lif_kernel<1><<<dim3(D3 / 64, MB), 256, 2 * STAGE_BYTES>>>(
            S2OFF, W3OFF, b3, M3OFF, S3OFF, (float*)0, (float*)0, D3, D2);

        mma_lif_kernel<1><<<dim3(D4 / 64, MB), 256, 2 * STAGE_BYTES>>>(
            S3OFF, W4OFF, b4, M4OFF, S4OFF, (float*)0, (float*)0, D4, D3);

        mma_lif_kernel<2><<<dim3(D5P / 64, MB), 256, 2 * STAGE_BYTES>>>(
            S4OFF, W5OFF, b5, M5OFF, 0,
            out_spk + (size_t)t * BATCH * D5,
            out_mem + (size_t)t * BATCH * D5, D5, D4);
    }
}

// round 11
// speedup vs baseline: 5.9006x; 1.6617x over previous
#include <cuda_runtime.h>
#include <cuda_fp16.h>
#include <stdint.h>
#include <math.h>

#define BATCH 2048
#define TSTEPS 25
#define MROWS (TSTEPS * BATCH)       // 51200
#define D0 100
#define D1 128
#define D2 256
#define D3 512
#define D4 1024
#define D5 784
#define D5P 832

#define BETA 0.95f
#define THRESH 1.0f
#define H2SCALE 2048.0f
#define H2INV (1.0f / 2048.0f)

// ------------------------- persistent device state -------------------------
__device__ float g_cur1[BATCH * D1];

// time-batched activation / current slabs
__device__ __half g_spkA[(size_t)MROWS * D4];     // layers 2,4 inputs
__device__ __half g_spkB[(size_t)MROWS * D4];     // layers 3,5 inputs
__device__ float  g_cur[(size_t)MROWS * D4];      // per-layer GEMM output (reused)

// 2-term fp16 split weights (h2 pre-scaled by 2^11)
#define W2OFF 0
#define W3OFF (W2OFF + D2*D1)
#define W4OFF (W3OFF + D3*D2)
#define W5OFF (W4OFF + D4*D3)
#define WTOTAL (W5OFF + D5P*D4)
__device__ __half g_h1[WTOTAL];
__device__ __half g_h2[WTOTAL];

// ------------------------------ utilities ----------------------------------
__global__ void split_w_kernel(const float* __restrict__ W, int N, int K,
                               int Npad, int off)
{
    int stride = gridDim.x * blockDim.x;
    int total = Npad * K;
    int nk = N * K;
    for (int i = blockIdx.x * blockDim.x + threadIdx.x; i < total; i += stride) {
        float w = 0.0f;
        if (i < nk) { w = W[i]; }
        __half h1 = __float2half(w);
        float r1 = w - __half2float(h1);
        g_h1[off + i] = h1;
        g_h2[off + i] = __float2half(r1 * H2SCALE);
    }
}

// layer-1 scan: cur1 constant over time; emit spk1 for all 25 steps
__global__ void lif1_scan_kernel()
{
    int idx = blockIdx.x * blockDim.x + threadIdx.x;   // 0 .. 2048*128-1
    if (idx < BATCH * D1) {
        float cur = g_cur1[idx];
        float mem = 0.0f;
#pragma unroll
        for (int t = 0; t < TSTEPS; t++) {
            float rst = (mem > THRESH) ? 1.0f : 0.0f;
            mem = BETA * mem + cur - rst * THRESH;
            float sp = (mem > THRESH) ? 1.0f : 0.0f;
            g_spkA[(size_t)t * (BATCH * D1) + idx] = __float2half(sp);
        }
    }
}

// generic LIF scan: g_cur [25*2048, N] fp32 -> spikes [25*2048, N] fp16
// sbuf: 0 -> g_spkA, 1 -> g_spkB   (pointer resolved in DEVICE code)
__global__ void lif_scan_kernel(int sbuf, int N)
{
    __half* spk = (sbuf == 0) ? g_spkA : g_spkB;
    int idx = blockIdx.x * blockDim.x + threadIdx.x;   // 0 .. 2048*N-1
    size_t stride = (size_t)BATCH * N;
    float mem = 0.0f;
#pragma unroll
    for (int t = 0; t < TSTEPS; t++) {
        float cur = g_cur[(size_t)t * stride + idx];
        float rst = (mem > THRESH) ? 1.0f : 0.0f;
        mem = BETA * mem + cur - rst * THRESH;
        float sp = (mem > THRESH) ? 1.0f : 0.0f;
        spk[(size_t)t * stride + idx] = __float2half(sp);
    }
}

// layer-5 scan: g_cur [25*2048, 832] -> out_spk / tanh(mem) [25, 2048, 784]
__global__ void lif5_scan_kernel(float* __restrict__ out_spk,
                                 float* __restrict__ out_mem)
{
    int idx = blockIdx.x * blockDim.x + threadIdx.x;   // 0 .. 2048*784-1
    int b = idx / D5;
    int n = idx - b * D5;
    size_t cbase = (size_t)b * D5P + n;
    size_t cstep = (size_t)BATCH * D5P;
    size_t ostep = (size_t)BATCH * D5;
    float mem = 0.0f;
#pragma unroll
    for (int t = 0; t < TSTEPS; t++) {
        float cur = g_cur[cbase + (size_t)t * cstep];
        float rst = (mem > THRESH) ? 1.0f : 0.0f;
        mem = BETA * mem + cur - rst * THRESH;
        float sp = (mem > THRESH) ? 1.0f : 0.0f;
        out_spk[(size_t)t * ostep + idx] = sp;
        out_mem[(size_t)t * ostep + idx] = tanhf(mem);
    }
}

// ----------------- layer-1 fp32 GEMM (runs once per launch) ----------------
__global__ __launch_bounds__(256)
void cur1_kernel(const float* __restrict__ A, const float* __restrict__ W,
                 const float* __restrict__ bias)
{
    const int N = D1;
    const int K = D0;
    __shared__ float As[16][128];
    __shared__ float Ws[16][64];

    int tid = threadIdx.x;
    int tx = tid & 15;
    int ty = tid >> 4;
    int m0 = blockIdx.y * 128;
    int n0 = blockIdx.x * 64;

    float acc[8][4];
#pragma unroll
    for (int i = 0; i < 8; i++) {
#pragma unroll
        for (int j = 0; j < 4; j++) { acc[i][j] = 0.0f; }
    }

    for (int k0 = 0; k0 < K; k0 += 16) {
#pragma unroll
        for (int it = 0; it < 2; it++) {
            int f4 = it * 256 + tid;
            int row = f4 >> 2;
            int q = f4 & 3;
            int gk = k0 + q * 4;
            float4 v = make_float4(0.f, 0.f, 0.f, 0.f);
            if (gk < K) {
                v = *reinterpret_cast<const float4*>(&A[(size_t)(m0 + row) * K + gk]);
            }
            As[q*4+0][row] = v.x;
            As[q*4+1][row] = v.y;
            As[q*4+2][row] = v.z;
            As[q*4+3][row] = v.w;
        }
        {
            int row = tid >> 2;
            int q = tid & 3;
            int gk = k0 + q * 4;
            float4 v = make_float4(0.f, 0.f, 0.f, 0.f);
            if (gk < K) {
                v = *reinterpret_cast<const float4*>(&W[(size_t)(n0 + row) * K + gk]);
            }
            Ws[q*4+0][row] = v.x;
            Ws[q*4+1][row] = v.y;
            Ws[q*4+2][row] = v.z;
            Ws[q*4+3][row] = v.w;
        }
        __syncthreads();
#pragma unroll
        for (int kk = 0; kk < 16; kk++) {
            float av[8];
            float wv[4];
#pragma unroll
            for (int i = 0; i < 8; i++) { av[i] = As[kk][ty * 8 + i]; }
#pragma unroll
            for (int j = 0; j < 4; j++) { wv[j] = Ws[kk][tx * 4 + j]; }
#pragma unroll
            for (int i = 0; i < 8; i++) {
#pragma unroll
                for (int j = 0; j < 4; j++) {
                    acc[i][j] = fmaf(av[i], wv[j], acc[i][j]);
                }
            }
        }
        __syncthreads();
    }

#pragma unroll
    for (int i = 0; i < 8; i++) {
        int gm = m0 + ty * 8 + i;
#pragma unroll
        for (int j = 0; j < 4; j++) {
            int gn = n0 + tx * 4 + j;
            g_cur1[(size_t)gm * N + gn] = fmaxf(acc[i][j] + bias[gn], 0.0f);
        }
    }
}

// ------------------- tensor-core GEMM (mma.sync, fp16 2-term) --------------
#define SWZ(x) ((x) ^ (((x) >> 3) & 0x70))
#define STAGE_BYTES 24576

__device__ __forceinline__ void cp16(uint32_t s, const void* g)
{
    asm volatile("cp.async.cg.shared.global [%0], [%1], 16;" :: "r"(s), "l"(g));
}

__device__ __forceinline__ void ldsm4(uint32_t* r, uint32_t s)
{
    asm volatile("ldmatrix.sync.aligned.m8n8.x4.shared.b16 {%0,%1,%2,%3}, [%4];"
                 : "=r"(r[0]), "=r"(r[1]), "=r"(r[2]), "=r"(r[3]) : "r"(s));
}

__device__ __forceinline__ void mma_f16(float* c, const uint32_t* a, const uint32_t* b)
{
    asm volatile("mma.sync.aligned.m16n8k16.row.col.f32.f16.f16.f32 "
                 "{%0,%1,%2,%3}, {%4,%5,%6,%7}, {%8,%9}, {%0,%1,%2,%3};"
                 : "+f"(c[0]), "+f"(c[1]), "+f"(c[2]), "+f"(c[3])
                 : "r"(a[0]), "r"(a[1]), "r"(a[2]), "r"(a[3]),
                   "r"(b[0]), "r"(b[1]));
}

// C[M=51200, N] = A[M,K] @ (h1 + h2/2048)[N,K]^T ; relu(+bias) -> g_cur
// abuf: 0 -> g_spkA, 1 -> g_spkB   (pointer resolved in DEVICE code)
__global__ __launch_bounds__(256)
void gemm_kernel(int abuf, int woff, const float* __restrict__ bias,
                 int N, int N_real, int K)
{
    extern __shared__ __align__(128) char smem_raw[];
    const uint32_t smem = (uint32_t)__cvta_generic_to_shared(smem_raw);

    const __half* __restrict__ A  = (abuf == 0) ? g_spkA : g_spkB;
    const __half* __restrict__ P1 = g_h1 + woff;
    const __half* __restrict__ P2 = g_h2 + woff;

    const int tid = threadIdx.x;
    const int lane = tid & 31;
    const int warp = tid >> 5;
    const int wm = warp >> 2;
    const int wn = warp & 3;
    const int m0 = blockIdx.y * 64;
    const int n0 = blockIdx.x * 64;

    float asum[2][2][4];
#pragma unroll
    for (int i = 0; i < 2; i++) {
#pragma unroll
        for (int j = 0; j < 2; j++) {
#pragma unroll
            for (int k = 0; k < 4; k++) { asum[i][j][k] = 0.0f; }
        }
    }

    const int crow = tid >> 3;
    const int ccol = tid & 7;
    const int nk = K >> 6;

    {
        uint32_t sA = smem;
        uint32_t s1 = smem + 8192;
        uint32_t s2 = smem + 16384;
#pragma unroll
        for (int it = 0; it < 2; it++) {
            int row = it * 32 + crow;
            uint32_t d = SWZ(row * 128 + ccol * 16);
            cp16(sA + d, A  + (size_t)(m0 + row) * K + ccol * 8);
            cp16(s1 + d, P1 + (size_t)(n0 + row) * K + ccol * 8);
            cp16(s2 + d, P2 + (size_t)(n0 + row) * K + ccol * 8);
        }
        asm volatile("cp.async.commit_group;");
    }

    const int arow = wm * 32 + (lane & 15);
    const int akc = lane >> 4;
    const int bq = lane >> 3;
    const int brow = wn * 16 + ((bq >> 1) << 3) + (lane & 7);
    const int bkc = bq & 1;

    for (int i = 0; i < nk; i++) {
        if (i + 1 < nk) {
            int k0 = (i + 1) << 6;
            uint32_t base = smem + ((i + 1) & 1) * STAGE_BYTES;
            uint32_t sA = base;
            uint32_t s1 = base + 8192;
            uint32_t s2 = base + 16384;
#pragma unroll
            for (int it = 0; it < 2; it++) {
                int row = it * 32 + crow;
                uint32_t d = SWZ(row * 128 + ccol * 16);
                cp16(sA + d, A  + (size_t)(m0 + row) * K + k0 + ccol * 8);
                cp16(s1 + d, P1 + (size_t)(n0 + row) * K + k0 + ccol * 8);
                cp16(s2 + d, P2 + (size_t)(n0 + row) * K + k0 + ccol * 8);
            }
            asm volatile("cp.async.commit_group;");
            asm volatile("cp.async.wait_group 1;");
        } else {
            asm volatile("cp.async.wait_group 0;");
        }
        __syncthreads();

        // fresh per-k-block accumulators (short, well-scaled TC chains)
        float accA[2][2][4];
        float accB[2][2][4];
#pragma unroll
        for (int ii = 0; ii < 2; ii++) {
#pragma unroll
            for (int jj = 0; jj < 2; jj++) {
#pragma unroll
                for (int kk2 = 0; kk2 < 4; kk2++) {
                    accA[ii][jj][kk2] = 0.0f;
                    accB[ii][jj][kk2] = 0.0f;
                }
            }
        }

        uint32_t base = smem + (i & 1) * STAGE_BYTES;
        uint32_t sA = base;
        uint32_t s1 = base + 8192;
        uint32_t s2 = base + 16384;
#pragma unroll
        for (int kk = 0; kk < 4; kk++) {
            uint32_t af[2][4];
            uint32_t b1[4];
            uint32_t b2[4];
#pragma unroll
            for (int mi = 0; mi < 2; mi++) {
                ldsm4(af[mi], sA + SWZ((arow + mi * 16) * 128 + (kk * 2 + akc) * 16));
            }
            ldsm4(b1, s1 + SWZ(brow * 128 + (kk * 2 + bkc) * 16));
            ldsm4(b2, s2 + SWZ(brow * 128 + (kk * 2 + bkc) * 16));
#pragma unroll
            for (int mi = 0; mi < 2; mi++) {
                mma_f16(accA[mi][0], af[mi], b1);
                mma_f16(accA[mi][1], af[mi], b1 + 2);
                mma_f16(accB[mi][0], af[mi], b2);
                mma_f16(accB[mi][1], af[mi], b2 + 2);
            }
        }

        // fold with exact fp32 RN ops; h2 term de-scaled
#pragma unroll
        for (int ii = 0; ii < 2; ii++) {
#pragma unroll
            for (int jj = 0; jj < 2; jj++) {
#pragma unroll
                for (int kk2 = 0; kk2 < 4; kk2++) {
                    asum[ii][jj][kk2] += fmaf(accB[ii][jj][kk2], H2INV,
                                              accA[ii][jj][kk2]);
                }
            }
        }
        __syncthreads();
    }

    // epilogue: relu(asum + bias) -> g_cur
#pragma unroll
    for (int mi = 0; mi < 2; mi++) {
        int rbase = m0 + wm * 32 + mi * 16 + (lane >> 2);
#pragma unroll
        for (int nf = 0; nf < 2; nf++) {
            int col = n0 + wn * 16 + nf * 8 + (lane & 3) * 2;
            float bia0 = (col < N_real) ? bias[col] : 0.0f;
            float bia1 = (col + 1 < N_real) ? bias[col + 1] : 0.0f;
#pragma unroll
            for (int h = 0; h < 2; h++) {
                int row = rbase + h * 8;
                float cu0 = fmaxf(asum[mi][nf][h * 2 + 0] + bia0, 0.0f);
                float cu1 = fmaxf(asum[mi][nf][h * 2 + 1] + bia1, 0.0f);
                *reinterpret_cast<float2*>(&g_cur[(size_t)row * N + col]) =
                    make_float2(cu0, cu1);
            }
        }
    }
}

// ------------------------------ host launcher ------------------------------
extern "C" void kernel_launch(void* const* d_in, const int* in_sizes, int n_in,
                              void* d_out, int out_size)
{
    const float* x  = (const float*)d_in[0];
    const float* W1 = (const float*)d_in[1];
    const float* b1 = (const float*)d_in[2];
    const float* W2 = (const float*)d_in[3];
    const float* b2 = (const float*)d_in[4];
    const float* W3 = (const float*)d_in[5];
    const float* b3 = (const float*)d_in[6];
    const float* W4 = (const float*)d_in[7];
    const float* b4 = (const float*)d_in[8];
    const float* W5 = (const float*)d_in[9];
    const float* b5 = (const float*)d_in[10];

    float* out = (float*)d_out;
    float* out_spk = out;
    float* out_mem = out + (size_t)TSTEPS * BATCH * D5;

    static int smem_set = 0;
    if (smem_set == 0) {
        cudaFuncSetAttribute(gemm_kernel,
                             cudaFuncAttributeMaxDynamicSharedMemorySize,
                             2 * STAGE_BYTES);
        smem_set = 1;
    }

    // weight splits
    split_w_kernel<<<128, 256>>>(W2, D2, D1, D2, W2OFF);
    split_w_kernel<<<256, 256>>>(W3, D3, D2, D3, W3OFF);
    split_w_kernel<<<512, 256>>>(W4, D4, D3, D4, W4OFF);
    split_w_kernel<<<896, 256>>>(W5, D5, D4, D5P, W5OFF);

    // layer 1: constant current, then full 25-step spike train
    cur1_kernel<<<dim3(2, 16), 256>>>(x, W1, b1);
    lif1_scan_kernel<<<(BATCH * D1) / 256, 256>>>();

    const int MB = MROWS / 64;   // 800

    // layer 2: GEMM over all timesteps (A = g_spkA), then scan -> g_spkB
    gemm_kernel<<<dim3(D2 / 64, MB), 256, 2 * STAGE_BYTES>>>(
        0, W2OFF, b2, D2, D2, D1);
    lif_scan_kernel<<<(BATCH * D2) / 256, 256>>>(1, D2);

    // layer 3 (A = g_spkB) -> scan -> g_spkA
    gemm_kernel<<<dim3(D3 / 64, MB), 256, 2 * STAGE_BYTES>>>(
        1, W3OFF, b3, D3, D3, D2);
    lif_scan_kernel<<<(BATCH * D3) / 256, 256>>>(0, D3);

    // layer 4 (A = g_spkA) -> scan -> g_spkB
    gemm_kernel<<<dim3(D4 / 64, MB), 256, 2 * STAGE_BYTES>>>(
        0, W4OFF, b4, D4, D4, D3);
    lif_scan_kernel<<<(BATCH * D4) / 256, 256>>>(1, D4);

    // layer 5 (A = g_spkB, padded N), then output scan
    gemm_kernel<<<dim3(D5P / 64, MB), 256, 2 * STAGE_BYTES>>>(
        1, W5OFF, b5, D5P, D5, D4);
    lif5_scan_kernel<<<(BATCH * D5) / 256, 256>>>(out_spk, out_mem);
}